// round 2
// baseline (speedup 1.0000x reference)
#include <cuda_runtime.h>
#include <cuda_bf16.h>

// ---------------- problem constants ----------------
#define B_BATCH 64
#define N_NODES 1024
#define S_LOC   12
#define HID     64
#define PAT     32
#define M_GLB   64
#define S_GLB   6
#define M_LOC   64
#define D_EMB   16
#define KDIM    768           // S_LOC * HID
#define CDIM    128           // M_LOC + M_GLB
#define ROWS    65536         // B_BATCH * N_NODES

// ---------------- static device scratch (no allocations allowed) ----------------
__device__ __align__(16) float g_A[KDIM * CDIM];          // folded weights  [768][128]
__device__ __align__(16) float g_bias[CDIM];              // b_q contribution to logits
__device__ __align__(16) float g_Lm[M_LOC * PAT];         // local bank mean  [64][32]
__device__ __align__(16) float g_Gm[M_GLB * PAT];         // global bank mean [64][32]
__device__ __align__(16) float g_nw[N_NODES * 64 * HID];  // node weights [1024][64][64]
__device__ __align__(16) float g_sim[(size_t)ROWS * CDIM];// logits [65536][128]

// ================= P1: A[k][c] = folded bank weights =================
// k = s*64 + h.  c<64: local  A = sum_p Wq[h][p]*L[c][s][p]
//                c>=64: global A = 0.5 * sum_p Wq[h][p]*G[c-64][s/2][p]
__global__ void pA_kernel(const float* __restrict__ G, const float* __restrict__ L,
                          const float* __restrict__ Wq) {
    int t = blockIdx.x * 256 + threadIdx.x;          // < 98304 = 768*128
    int k = t >> 7, c = t & 127;
    int s = k >> 6, h = k & 63;
    const float* wp = Wq + h * PAT;
    float v = 0.f;
    if (c < 64) {
        const float* lp = L + c * (S_LOC * PAT) + s * PAT;
        #pragma unroll
        for (int p = 0; p < PAT; p++) v += wp[p] * lp[p];
    } else {
        const float* gp = G + (c - 64) * (S_GLB * PAT) + (s >> 1) * PAT;
        #pragma unroll
        for (int p = 0; p < PAT; p++) v += wp[p] * gp[p];
        v *= 0.5f;
    }
    g_A[k * CDIM + c] = v;
}

// ================= P2: bias[c] = b_q contribution =================
__global__ void pBias_kernel(const float* __restrict__ G, const float* __restrict__ L,
                             const float* __restrict__ bq) {
    int c = threadIdx.x;                              // 128 threads
    float v = 0.f;
    if (c < 64) {
        for (int s = 0; s < S_LOC; s++)
            #pragma unroll
            for (int p = 0; p < PAT; p++) v += bq[p] * L[c * (S_LOC * PAT) + s * PAT + p];
    } else {
        // pooled-q dot G: bias of pooled q is just b_q (mean of constant)
        for (int s = 0; s < S_GLB; s++)
            #pragma unroll
            for (int p = 0; p < PAT; p++) v += bq[p] * G[(c - 64) * (S_GLB * PAT) + s * PAT + p];
    }
    g_bias[c] = v;
}

// ================= P3: bank means over s =================
__global__ void pMean_kernel(const float* __restrict__ G, const float* __restrict__ L) {
    int idx = blockIdx.x * 256 + threadIdx.x;         // < 2048
    if (idx >= 2048) return;
    int m = idx >> 5, p = idx & 31;
    float lm = 0.f, gm = 0.f;
    for (int s = 0; s < S_LOC; s++) lm += L[m * (S_LOC * PAT) + s * PAT + p];
    for (int s = 0; s < S_GLB; s++) gm += G[m * (S_GLB * PAT) + s * PAT + p];
    g_Lm[idx] = lm * (1.f / 12.f);
    g_Gm[idx] = gm * (1.f / 6.f);
}

// ================= P4: node_w[n][f][h] = sum_d emb[n][d]*pool[d][f][h] =================
__global__ void pNw_kernel(const float* __restrict__ emb, const float* __restrict__ pool) {
    __shared__ float e[D_EMB];
    int n = blockIdx.x, t = threadIdx.x;
    if (t < D_EMB) e[t] = emb[n * D_EMB + t];
    __syncthreads();
    #pragma unroll
    for (int j = 0; j < 16; j++) {
        int idx = j * 256 + t;                        // f*64 + h, < 4096
        float v = 0.f;
        #pragma unroll
        for (int d = 0; d < D_EMB; d++) v += e[d] * pool[d * 4096 + idx];
        g_nw[n * 4096 + idx] = v;
    }
}

// ================= K1: g_sim = H @ g_A + bias =================
// 512 blocks x 256 threads; block tile 128x128, k-tile 16, thread tile 8x8.
__global__ __launch_bounds__(256) void k1_gemm(const float* __restrict__ H) {
    __shared__ float As[16][128];   // H tile, transposed
    __shared__ float Bs[16][128];   // A tile, natural
    int tid = threadIdx.x;
    int row0 = blockIdx.x << 7;
    int ty = tid >> 4, tx = tid & 15;
    float acc[8][8] = {};
    const float* Hb = H + (size_t)row0 * KDIM;

    for (int kt = 0; kt < KDIM; kt += 16) {
        #pragma unroll
        for (int i = 0; i < 2; i++) {
            int id = tid + i * 256;                   // < 512 float4
            int m = id >> 2, kk = (id & 3) << 2;
            float4 v = *(const float4*)(Hb + (size_t)m * KDIM + kt + kk);
            As[kk + 0][m] = v.x; As[kk + 1][m] = v.y;
            As[kk + 2][m] = v.z; As[kk + 3][m] = v.w;
        }
        #pragma unroll
        for (int i = 0; i < 2; i++) {
            int id = tid + i * 256;
            int k = id >> 5, n4 = (id & 31) << 2;
            *(float4*)&Bs[k][n4] = *(const float4*)(g_A + (kt + k) * CDIM + n4);
        }
        __syncthreads();
        #pragma unroll
        for (int k = 0; k < 16; k++) {
            float4 a0 = *(float4*)&As[k][ty * 8];
            float4 a1 = *(float4*)&As[k][ty * 8 + 4];
            float4 b0 = *(float4*)&Bs[k][tx * 8];
            float4 b1 = *(float4*)&Bs[k][tx * 8 + 4];
            float a[8] = {a0.x,a0.y,a0.z,a0.w,a1.x,a1.y,a1.z,a1.w};
            float b[8] = {b0.x,b0.y,b0.z,b0.w,b1.x,b1.y,b1.z,b1.w};
            #pragma unroll
            for (int i = 0; i < 8; i++)
                #pragma unroll
                for (int j = 0; j < 8; j++) acc[i][j] += a[i] * b[j];
        }
        __syncthreads();
    }
    #pragma unroll
    for (int i = 0; i < 8; i++) {
        size_t r = row0 + ty * 8 + i;
        float* op = g_sim + r * CDIM + tx * 8;
        #pragma unroll
        for (int j = 0; j < 8; j++) op[j] = acc[i][j] + g_bias[tx * 8 + j];
    }
}

// ================= K2: softmax + context + per-node projection =================
// 1024 blocks (one per node n), 8 warps; each warp handles 8 batch rows.
__global__ __launch_bounds__(256) void k2_epi(float* __restrict__ out) {
    __shared__ float snw[64][64];    // node_w[n]
    __shared__ float sLm[64][32];
    __shared__ float sGm[64][32];
    __shared__ float sattn[8][128];
    __shared__ float sfused[8][64];

    int n = blockIdx.x, tid = threadIdx.x;
    int w = tid >> 5, lane = tid & 31;

    // stage node weights + bank means
    {
        const float4* src = (const float4*)(g_nw + (size_t)n * 4096);
        float4* dst = (float4*)&snw[0][0];
        #pragma unroll
        for (int i = 0; i < 4; i++) dst[tid + i * 256] = src[tid + i * 256];
        float* lm = &sLm[0][0]; float* gm = &sGm[0][0];
        for (int i = tid; i < 2048; i += 256) { lm[i] = g_Lm[i]; gm[i] = g_Gm[i]; }
    }
    __syncthreads();

    for (int i = 0; i < 8; i++) {
        int b = i * 8 + w;
        size_t row = (size_t)b * N_NODES + n;
        const float* sp = g_sim + row * CDIM;
        float v0 = sp[lane], v1 = sp[lane + 32];          // local logits
        float v2 = sp[lane + 64], v3 = sp[lane + 96];     // global logits

        // local softmax (64 wide)
        float mx = fmaxf(v0, v1);
        #pragma unroll
        for (int o = 16; o; o >>= 1) mx = fmaxf(mx, __shfl_xor_sync(0xffffffffu, mx, o));
        float e0 = __expf(v0 - mx), e1 = __expf(v1 - mx);
        float s = e0 + e1;
        #pragma unroll
        for (int o = 16; o; o >>= 1) s += __shfl_xor_sync(0xffffffffu, s, o);
        float inv = 1.f / s;
        sattn[w][lane] = e0 * inv; sattn[w][lane + 32] = e1 * inv;

        // global softmax (64 wide)
        mx = fmaxf(v2, v3);
        #pragma unroll
        for (int o = 16; o; o >>= 1) mx = fmaxf(mx, __shfl_xor_sync(0xffffffffu, mx, o));
        float e2 = __expf(v2 - mx), e3 = __expf(v3 - mx);
        s = e2 + e3;
        #pragma unroll
        for (int o = 16; o; o >>= 1) s += __shfl_xor_sync(0xffffffffu, s, o);
        inv = 1.f / s;
        sattn[w][64 + lane] = e2 * inv; sattn[w][96 + lane] = e3 * inv;
        __syncwarp();

        // contexts: lane owns pattern p = lane
        float lctx = 0.f, gctx = 0.f;
        #pragma unroll 8
        for (int m = 0; m < 64; m++) {
            lctx += sattn[w][m]      * sLm[m][lane];
            gctx += sattn[w][64 + m] * sGm[m][lane];
        }
        sfused[w][lane] = lctx; sfused[w][lane + 32] = gctx;
        __syncwarp();

        // out[row][h] = sum_f fused[f] * nw[f][h]; lane covers h=lane, lane+32
        float o0 = 0.f, o1 = 0.f;
        #pragma unroll 8
        for (int f = 0; f < 64; f++) {
            float fv = sfused[w][f];
            o0 += fv * snw[f][lane];
            o1 += fv * snw[f][lane + 32];
        }
        float* op = out + row * HID;
        op[lane] = o0; op[lane + 32] = o1;
        __syncwarp();
    }
}

// ================= launch =================
extern "C" void kernel_launch(void* const* d_in, const int* in_sizes, int n_in,
                              void* d_out, int out_size) {
    const float* H    = (const float*)d_in[0];   // [64,1024,12,64]
    const float* G    = (const float*)d_in[1];   // [64,6,32]
    const float* L    = (const float*)d_in[2];   // [64,12,32]
    const float* Wq   = (const float*)d_in[3];   // [64,32]
    const float* bq   = (const float*)d_in[4];   // [32]
    const float* emb  = (const float*)d_in[5];   // [1024,16]
    const float* pool = (const float*)d_in[6];   // [16,64,64]
    float* out = (float*)d_out;                  // [64,1024,64]

    pA_kernel  <<<384, 256>>>(G, L, Wq);
    pBias_kernel<<<1, 128>>>(G, L, bq);
    pMean_kernel<<<8, 256>>>(G, L);
    pNw_kernel <<<N_NODES, 256>>>(emb, pool);
    k1_gemm    <<<ROWS / 128, 256>>>(H);
    k2_epi     <<<N_NODES, 256>>>(out);
}